// round 16
// baseline (speedup 1.0000x reference)
#include <cuda_runtime.h>
#include <cuda_bf16.h>
#include <math.h>
#include <stdint.h>

#define N_NODES 2048
#define N_EDGES 49152
#define HID     80
#define AGGD    96
#define WN      3328
#define EPB     128
#define SP      132

__device__ float g_geo[N_EDGES * 20];
__device__ __nv_bfloat16 g_f2h[4L * N_EDGES * 64];
__device__ __nv_bfloat16 g_w3h[104L * 8192];
__device__ float g_b3r[104 * 128];
__device__ float g_h    [N_NODES * HID];
__device__ float g_hx   [N_NODES * HID];
__device__ float g_xself[N_NODES * HID];
__device__ float g_agg  [N_NODES * AGGD];

__device__ __forceinline__ unsigned s2u(const void* p) {
    unsigned a;
    asm("{ .reg .u64 t; cvta.to.shared.u64 t, %1; cvt.u32.u64 %0, t; }" : "=r"(a) : "l"(p));
    return a;
}
__device__ __forceinline__ void ldsm4(uint32_t* r, unsigned addr) {
    asm volatile("ldmatrix.sync.aligned.m8n8.x4.shared.b16 {%0,%1,%2,%3}, [%4];"
                 : "=r"(r[0]), "=r"(r[1]), "=r"(r[2]), "=r"(r[3]) : "r"(addr));
}
__device__ __forceinline__ void mma16816(float* c, const uint32_t* a, uint32_t b0, uint32_t b1) {
    asm volatile("mma.sync.aligned.m16n8k16.row.col.f32.bf16.bf16.f32 "
                 "{%0,%1,%2,%3}, {%4,%5,%6,%7}, {%8,%9}, {%0,%1,%2,%3};"
                 : "+f"(c[0]), "+f"(c[1]), "+f"(c[2]), "+f"(c[3])
                 : "r"(a[0]), "r"(a[1]), "r"(a[2]), "r"(a[3]), "r"(b0), "r"(b1));
}
__device__ __forceinline__ void cpa16(unsigned dst, const void* src) {
    asm volatile("cp.async.ca.shared.global [%0], [%1], 16;" :: "r"(dst), "l"(src) : "memory");
}
#define CPA_COMMIT() asm volatile("cp.async.commit_group;" ::: "memory")
#define CPA_WAIT0()  asm volatile("cp.async.wait_group 0;" ::: "memory")

__device__ const int cb_[26]  = {0,0,0,0,0,0,0,0,0,0,0,0, 1536,1536,1536,1536,1536,1536,
                                 2304,2304,2304,2304, 2816,2816, 3072,3072};
__device__ const int cw_[26]  = {48,48,48,48,48,48,48,48,48,48,48,48, 48,48,48,48,48,48,
                                 16,16,16,16, 16,16, 16,16};
__device__ const int cnu_[26] = {32,32,32,32,32,32,32,32,32,32,32,32, 16,16,16,16,16,16,
                                 32,32,32,32, 16,16, 16,16};
__device__ const int cwb_[26] = {0,4,8,12,16,20,24,28,32,36,40,44, 0,8,16,24,32,40,
                                 0,4,8,12, 0,8, 0,8};
__device__ const int cbk_[26] = {0,0,0,0,0,0,0,0,0,0,0,0, 1,1,1,1,1,1, 2,2,2,2, 3,3, 4,4};

// ---------------- kA: geometry + embed-init + W3 pre-split ----------------
__global__ void kA(const float* __restrict__ pos, const int* __restrict__ ei,
                   const float* __restrict__ x, const float* __restrict__ ew,
                   const float* __restrict__ W3, const float* __restrict__ B3) {
    if (blockIdx.x < 192) {
        int e = blockIdx.x*256 + threadIdx.x;
        int s = ei[e], d = ei[N_EDGES + e];
        float rx = pos[d*3+0]-pos[s*3+0], ry = pos[d*3+1]-pos[s*3+1], rz = pos[d*3+2]-pos[s*3+2];
        float r = fmaxf(sqrtf(rx*rx+ry*ry+rz*rz), 1e-6f);
        float inv = 1.f/r;
        float dx = rx*inv, dy = ry*inv, dz = rz*inv;
        float* g = g_geo + e*20;
        const float s3 = 1.7320508075688772f;
        g[0]=s3*dx; g[1]=s3*dy; g[2]=s3*dz;
        const float c15 = 3.872983346207417f;
        float y20=c15*dx*dy, y21=c15*dy*dz, y22=1.1180339887498949f*(3.f*dz*dz-1.f);
        float y23=c15*dx*dz, y24=0.5f*c15*(dx*dx-dy*dy);
        const float s2=0.7071067811865476f, s6=0.4082482904638631f, q=0.7745966692414834f;
        g[3]=q*(-s6*y22+s2*y24); g[4]=q*(-s6*y22-s2*y24); g[5]=q*(2.f*s6*y22);
        g[6]=q*s2*y20; g[7]=q*s2*y21; g[8]=q*s2*y23;
        float u = r*(1.f/6.f);
        float u3=u*u*u, u6=u3*u3, u7=u6*u, u8=u7*u;
        float fc = (u<1.f) ? (1.f-28.f*u6+48.f*u7-21.f*u8) : 0.f;
        float pref = 0.5773502691896258f*inv*fc;
        float pir = 3.14159265358979323846f*r*(1.f/6.f);
        #pragma unroll
        for (int n = 1; n <= 8; ++n) g[8+n] = pref*sinf((float)n*pir);
    } else if (blockIdx.x < 832) {
        int idx = (blockIdx.x-192)*256 + threadIdx.x;
        if (idx >= N_NODES*HID) return;
        int n = idx/HID, c = idx - n*HID;
        float v = 0.f;
        if (c < 32) {
            float a = 0.f;
            #pragma unroll
            for (int u = 0; u < 16; ++u) a = fmaf(x[n*16+u], ew[u*32+c], a);
            v = a*0.25f;
        }
        g_h[idx] = v;
    } else {
        int b = blockIdx.x - 832;
        int l = b / 26, c = b - l*26;
        int base = cb_[c], W = cw_[c], nu = cnu_[c], wb = cwb_[c];
        const float* W3c = W3 + (size_t)l*64*WN;
        for (int i = threadIdx.x; i < 8192; i += 256) {
            int s = i >> 6, k = i & 63;
            int u, wo;
            if (nu == 32) { u = s & 31; wo = s >> 5; } else { u = s & 15; wo = s >> 4; }
            g_w3h[(size_t)b*8192 + i] = __float2bfloat16(W3c[(size_t)k*WN + base + u*W + wb + wo]);
        }
        if (threadIdx.x < 128) {
            int s = threadIdx.x, u, wo;
            if (nu == 32) { u = s & 31; wo = s >> 5; } else { u = s & 15; wo = s >> 4; }
            g_b3r[b*128 + s] = B3[l*WN + base + u*W + wb + wo];
        }
    }
}

// ---------------- radial MLP (all 4 layers), vectorized, bf16 output ----------------
__global__ __launch_bounds__(256)
void k_radial4(const float* __restrict__ W1, const float* __restrict__ B1,
               const float* __restrict__ W2, const float* __restrict__ B2) {
    __shared__ float w1s[512], b1s[64], w2s[4096], b2s[64];
    int tid = threadIdx.x;
    int l = blockIdx.x / 192;
    int e = (blockIdx.x - l*192)*256 + tid;
    const float* W1l = W1 + l*512; const float* W2l = W2 + l*4096;
    for (int i = tid; i < 512;  i += 256) w1s[i]=W1l[i];
    for (int i = tid; i < 4096; i += 256) w2s[i]=W2l[i];
    if (tid < 64) { b1s[tid]=B1[l*64+tid]; b2s[tid]=B2[l*64+tid]; }
    __syncthreads();
    float rbf[8];
    #pragma unroll
    for (int n = 0; n < 8; ++n) rbf[n] = g_geo[e*20+9+n];
    float f1[64];
    #pragma unroll
    for (int o4 = 0; o4 < 16; ++o4) {
        float4 acc = *(const float4*)&b1s[o4*4];
        #pragma unroll
        for (int n = 0; n < 8; ++n) {
            float4 w = *(const float4*)&w1s[n*64 + o4*4];
            float f = rbf[n];
            acc.x = fmaf(f,w.x,acc.x); acc.y = fmaf(f,w.y,acc.y);
            acc.z = fmaf(f,w.z,acc.z); acc.w = fmaf(f,w.w,acc.w);
        }
        f1[o4*4+0] = acc.x/(1.f+__expf(-acc.x));
        f1[o4*4+1] = acc.y/(1.f+__expf(-acc.y));
        f1[o4*4+2] = acc.z/(1.f+__expf(-acc.z));
        f1[o4*4+3] = acc.w/(1.f+__expf(-acc.w));
    }
    size_t ob = ((size_t)l*N_EDGES + e)*64;
    #pragma unroll
    for (int o4 = 0; o4 < 16; ++o4) {
        float4 acc = *(const float4*)&b2s[o4*4];
        #pragma unroll
        for (int k = 0; k < 64; ++k) {
            float4 w = *(const float4*)&w2s[k*64 + o4*4];
            float f = f1[k];
            acc.x = fmaf(f,w.x,acc.x); acc.y = fmaf(f,w.y,acc.y);
            acc.z = fmaf(f,w.z,acc.z); acc.w = fmaf(f,w.w,acc.w);
        }
        float s0 = acc.x/(1.f+__expf(-acc.x));
        float s1 = acc.y/(1.f+__expf(-acc.y));
        float s2 = acc.z/(1.f+__expf(-acc.z));
        float s3 = acc.w/(1.f+__expf(-acc.w));
        __nv_bfloat162 p0 = __floats2bfloat162_rn(s0, s1);
        __nv_bfloat162 p1 = __floats2bfloat162_rn(s2, s3);
        uint2 st;
        st.x = *reinterpret_cast<unsigned*>(&p0);
        st.y = *reinterpret_cast<unsigned*>(&p1);
        *reinterpret_cast<uint2*>(g_f2h + ob + o4*4) = st;
    }
}

// ---------------- fused gate(prev layer) + node linears + agg zero ----------------
__global__ __launch_bounds__(256)
void k_fuse(int do_gate, const float* __restrict__ Ws, const float* __restrict__ Wv,
            const float* __restrict__ Ss, const float* __restrict__ Sv) {
    __shared__ float ws_[1024], wv_[256], ss_[1024], sv_[256];
    int tid = threadIdx.x;
    int gid = blockIdx.x*256 + tid;
    int n = gid >> 3, slot = gid & 7;
    for (int i = tid; i < 1024; i += 256) { ws_[i]=Ws[i]; ss_[i]=Ss[i]; }
    if (tid < 256) { wv_[tid]=Wv[tid]; sv_[tid]=Sv[tid]; }
    if (do_gate) {
        #pragma unroll
        for (int cc = 0; cc < 10; ++cc) {
            int c = slot*10 + cc;
            float add;
            if (c < 32) {
                float a = g_agg[n*AGGD+c];
                add = a/(1.f+__expf(-a));
            } else {
                int c2 = c-32, w = c2/3;
                float gg = g_agg[n*AGGD+32+w];
                add = g_agg[n*AGGD+48+c2]/(1.f+__expf(-gg));
            }
            g_h[n*HID+c] = g_h[n*HID+c] + g_xself[n*HID+c] + add;
        }
    }
    __syncthreads();
    for (int i = tid; i < 32*AGGD; i += 256) g_agg[(size_t)blockIdx.x*32*AGGD + i] = 0.f;

    float hs[32], hv[48];
    #pragma unroll
    for (int i = 0; i < 32; ++i) hs[i] = g_h[n*HID+i];
    #pragma unroll
    for (int i = 0; i < 48; ++i) hv[i] = g_h[n*HID+32+i];
    const float is = 0.17677669529663687f, iv = 0.25f;
    #pragma unroll
    for (int c4 = 0; c4 < 4; ++c4) {
        int w = slot*4 + c4;
        float a=0.f, b=0.f;
        #pragma unroll
        for (int u = 0; u < 32; ++u) { a=fmaf(hs[u],ws_[u*32+w],a); b=fmaf(hs[u],ss_[u*32+w],b); }
        g_hx[n*HID+w]=a*is; g_xself[n*HID+w]=b*is;
    }
    #pragma unroll
    for (int c2 = 0; c2 < 2; ++c2) {
        int w = slot*2 + c2;
        float a0=0,a1=0,a2=0,b0=0,b1=0,b2=0;
        #pragma unroll
        for (int u = 0; u < 16; ++u) {
            float wl=wv_[u*16+w], sl=sv_[u*16+w];
            a0=fmaf(hv[u*3+0],wl,a0); a1=fmaf(hv[u*3+1],wl,a1); a2=fmaf(hv[u*3+2],wl,a2);
            b0=fmaf(hv[u*3+0],sl,b0); b1=fmaf(hv[u*3+1],sl,b1); b2=fmaf(hv[u*3+2],sl,b2);
        }
        g_hx[n*HID+32+w*3+0]=a0*iv; g_hx[n*HID+32+w*3+1]=a1*iv; g_hx[n*HID+32+w*3+2]=a2*iv;
        g_xself[n*HID+32+w*3+0]=b0*iv; g_xself[n*HID+32+w*3+1]=b1*iv; g_xself[n*HID+32+w*3+2]=b2*iv;
    }
}

// ---------------- k_msg ----------------
#define RP 72

struct SmemT {
    __nv_bfloat16 Ah[128*RP];
    __nv_bfloat16 Bh[2][128*RP];
    float bias[2][128];
    float sj[32*SP];
    float p2[16*SP];
    float vj[48*SP];
    float y1[3*SP];
    float Mq[6*SP];
    float t3[16*SP];
    float accs[48*SP];
    float accv[48*SP];
    int srcs[EPB];
    int dsts[EPB];
};

__global__ __launch_bounds__(512, 1)
void k_msg(int l, const int* __restrict__ ei) {
    extern __shared__ unsigned char smraw[];
    SmemT* sm = (SmemT*)smraw;
    int tid = threadIdx.x;
    int wid = tid >> 5, lid = tid & 31;
    int e0 = blockIdx.x * EPB;
    int l26 = l * 26;

    if (tid < EPB) { sm->srcs[tid] = ei[e0+tid]; sm->dsts[tid] = ei[N_EDGES+e0+tid]; }

    {
        unsigned ahU = s2u(sm->Ah);
        const char* sh = (const char*)(g_f2h + ((size_t)l*N_EDGES + e0)*64);
        for (int t = tid; t < 1024; t += 512) {
            int r = t >> 3, k8 = t & 7;
            cpa16(ahU + (unsigned)(r*144 + k8*16), sh + r*128 + k8*16);
        }
    }
    auto issueB = [&](int c) {
        unsigned bh = s2u(sm->Bh[c & 1]);
        const char* srch = (const char*)(g_w3h + (size_t)(l26 + c)*8192);
        for (int t = tid; t < 1024; t += 512) {
            int s = t >> 3, k8 = t & 7;
            cpa16(bh + (unsigned)(s*144 + k8*16), srch + s*128 + k8*16);
        }
        if (tid < 32) cpa16(s2u(&sm->bias[c & 1][0]) + tid*16,
                            (const char*)(g_b3r + (size_t)(l26 + c)*128) + tid*16);
        CPA_COMMIT();
    };
    issueB(0);
    __syncthreads();

    for (int i = tid; i < EPB*80; i += 512) {
        int ee = i/80, c = i - ee*80;
        float v = g_hx[sm->srcs[ee]*HID + c];
        if (c < 32) sm->sj[c*SP+ee] = v; else sm->vj[(c-32)*SP+ee] = v;
    }
    for (int i = tid; i < EPB*9; i += 512) {
        int ee = i/9, c = i - ee*9;
        float v = g_geo[(e0+ee)*20 + c];
        if (c < 3) sm->y1[c*SP+ee] = v; else sm->Mq[(c-3)*SP+ee] = v;
    }
    __syncthreads();
    for (int i = tid; i < EPB*16; i += 512) {
        int ee = i & 127, u = i >> 7;
        float v0 = sm->vj[(u*3+0)*SP+ee], v1 = sm->vj[(u*3+1)*SP+ee], v2 = sm->vj[(u*3+2)*SP+ee];
        sm->p2[u*SP+ee] = (v0*sm->y1[ee] + v1*sm->y1[SP+ee] + v2*sm->y1[2*SP+ee])
                          * 0.5773502691896258f;
    }

    int wq = wid >> 2;
    int rgrp = (wid & 3) * 32;
    int cg = wq * 32;
    int q = lid >> 2, ln4 = lid & 3;
    unsigned ahB = s2u(sm->Ah);
    unsigned a_off = (unsigned)((rgrp + (lid & 15))*144 + ((lid >> 4)*8)*2);
    unsigned b_off = (unsigned)((cg + ((lid >> 4)*8) + (lid & 7))*144 + (((lid >> 3) & 1)*8)*2);

    uint32_t AF[4][2][4];

    for (int c = 0; c < 26; ++c) {
        int wb = cwb_[c], bk = cbk_[c];
        CPA_WAIT0();
        __syncthreads();
        if (c == 0) {
            #pragma unroll
            for (int ks = 0; ks < 4; ++ks) {
                ldsm4(AF[ks][0], ahB + a_off + ks*32);
                ldsm4(AF[ks][1], ahB + a_off + 16*144 + ks*32);
            }
        }
        if (c < 25) issueB(c + 1);

        unsigned bhB = s2u(sm->Bh[c & 1]);
        const float* biasc = sm->bias[c & 1];

        float acc[2][4][4];
        #pragma unroll
        for (int i = 0; i < 2; ++i)
            #pragma unroll
            for (int j = 0; j < 4; ++j)
                #pragma unroll
                for (int k = 0; k < 4; ++k) acc[i][j][k] = 0.f;
        #pragma unroll
        for (int ks = 0; ks < 4; ++ks) {
            uint32_t Bh0[4], Bh1[4];
            ldsm4(Bh0, bhB + b_off + ks*32);
            ldsm4(Bh1, bhB + b_off + 16*144 + ks*32);
            uint32_t* Bhp[4] = {Bh0, Bh0+2, Bh1, Bh1+2};
            #pragma unroll
            for (int nt = 0; nt < 4; ++nt) {
                mma16816(acc[0][nt], AF[ks][0], Bhp[nt][0], Bhp[nt][1]);
                mma16816(acc[1][nt], AF[ks][1], Bhp[nt][0], Bhp[nt][1]);
            }
        }

        float bias8[8];
        #pragma unroll
        for (int nt = 0; nt < 4; ++nt)
            #pragma unroll
            for (int jj = 0; jj < 2; ++jj)
                bias8[nt*2+jj] = biasc[cg + nt*8 + ln4*2 + jj];

        if (bk == 0 || bk == 2) {
            #pragma unroll
            for (int i = 0; i < 4; ++i) {
                int er = rgrp + q + i*8;
                float p = 0.f;
                #pragma unroll
                for (int nt = 0; nt < 4; ++nt)
                    #pragma unroll
                    for (int jj = 0; jj < 2; ++jj) {
                        int u = nt*8 + ln4*2 + jj;
                        p = fmaf(acc[i>>1][nt][(i&1)*2+jj] + bias8[nt*2+jj],
                                 sm->sj[u*SP+er], p);
                    }
                p += __shfl_xor_sync(0xFFFFFFFFu, p, 1);
                p += __shfl_xor_sync(0xFFFFFFFFu, p, 2);
                if (ln4 == 0) {
                    if (bk == 0) sm->accs[(wb+wq)*SP+er] = p;
                    else         sm->t3[(wb+wq)*SP+er]   = p;
                }
            }
        } else if (bk == 1) {
            #pragma unroll
            for (int i = 0; i < 4; ++i) {
                int er = rgrp + q + i*8;
                #pragma unroll
                for (int h = 0; h < 2; ++h) {
                    float p = 0.f;
                    #pragma unroll
                    for (int n2 = 0; n2 < 2; ++n2) {
                        int nt = h*2 + n2;
                        #pragma unroll
                        for (int jj = 0; jj < 2; ++jj) {
                            int u = n2*8 + ln4*2 + jj;
                            p = fmaf(acc[i>>1][nt][(i&1)*2+jj] + bias8[nt*2+jj],
                                     sm->p2[u*SP+er], p);
                        }
                    }
                    p += __shfl_xor_sync(0xFFFFFFFFu, p, 1);
                    p += __shfl_xor_sync(0xFFFFFFFFu, p, 2);
                    if (ln4 == 0) sm->accs[(wb + wq*2 + h)*SP+er] += p;
                }
            }
        } else {
            #pragma unroll
            for (int i = 0; i < 4; ++i) {
                int er = rgrp + q + i*8;
                float M00=0,M11=0,M22=0,M01=0,M12=0,M02=0;
                if (bk == 4) {
                    M00=sm->Mq[er]; M11=sm->Mq[SP+er]; M22=sm->Mq[2*SP+er];
                    M01=sm->Mq[3*SP+er]; M12=sm->Mq[4*SP+er]; M02=sm->Mq[5*SP+er];
                }
                #pragma unroll
                for (int h = 0; h < 2; ++h) {
                    float a0=0.f, a1=0.f, a2=0.f;
                    #pragma unroll
                    for (int n2 = 0; n2 < 2; ++n2) {
                        int nt = h*2 + n2;
                        #pragma unroll
                        for (int jj = 0; jj < 2; ++jj) {
                            int u = n2*8 + ln4*2 + jj;
                            float bv = acc[i>>1][nt][(i&1)*2+jj] + bias8[nt*2+jj];
                            float v0 = sm->vj[(u*3+0)*SP+er];
                            float v1 = sm->vj[(u*3+1)*SP+er];
                            float v2 = sm->vj[(u*3+2)*SP+er];
                            float f0, f1, f2;
                            if (bk == 4) {
                                f0 = v0*M00 + v1*M01 + v2*M02;
                                f1 = v0*M01 + v1*M11 + v2*M12;
                                f2 = v0*M02 + v1*M12 + v2*M22;
                            } else { f0 = v0; f1 = v1; f2 = v2; }
                            a0 = fmaf(bv, f0, a0);
                            a1 = fmaf(bv, f1, a1);
                            a2 = fmaf(bv, f2, a2);
                        }
                    }
                    a0 += __shfl_xor_sync(0xFFFFFFFFu, a0, 1);
                    a0 += __shfl_xor_sync(0xFFFFFFFFu, a0, 2);
                    a1 += __shfl_xor_sync(0xFFFFFFFFu, a1, 1);
                    a1 += __shfl_xor_sync(0xFFFFFFFFu, a1, 2);
                    a2 += __shfl_xor_sync(0xFFFFFFFFu, a2, 1);
                    a2 += __shfl_xor_sync(0xFFFFFFFFu, a2, 2);
                    if (ln4 == 0) {
                        int w = wb + wq*2 + h;
                        if (bk == 3) {
                            sm->accv[(w*3+0)*SP+er] = a0;
                            sm->accv[(w*3+1)*SP+er] = a1;
                            sm->accv[(w*3+2)*SP+er] = a2;
                        } else {
                            sm->accv[(w*3+0)*SP+er] += a0;
                            sm->accv[(w*3+1)*SP+er] += a1;
                            sm->accv[(w*3+2)*SP+er] += a2;
                        }
                    }
                }
            }
        }
    }
    __syncthreads();

    const float SS = 0.029462782549439483f;
    const float SV = 0.025515518153991442f;
    int e = tid & 127, wp = tid >> 7;
    int dd = sm->dsts[e];
    for (int c = wp*24; c < wp*24+24; ++c) {
        float val;
        if (c < 48) val = sm->accs[c*SP+e]*SS;
        else {
            int cc = c-48, w = cc/3, i = cc-w*3;
            val = (sm->accv[cc*SP+e] + sm->y1[i*SP+e]*sm->t3[w*SP+e])*SV;
        }
        atomicAdd(&g_agg[dd*AGGD+c], val);
    }
}

// ---------------- final: gate + projection ----------------
__global__ __launch_bounds__(256)
void k_fin(const float* __restrict__ proj, float* __restrict__ out) {
    __shared__ float pj[1024];
    __shared__ float hsm[8][33];
    int tid = threadIdx.x;
    if (tid < 256) {
        pj[tid] = proj[tid]; pj[256+tid] = proj[256+tid];
        pj[512+tid] = proj[512+tid]; pj[768+tid] = proj[768+tid];
    }
    int n0 = blockIdx.x * 8;          // 8 nodes per block, 32 threads per node
    int nn = tid >> 5, j = tid & 31;
    int n = n0 + nn;
    // gate channel j (scalar part only needed for output; but h must be fully updated? proj uses h[:32] only)
    float a = g_agg[n*AGGD + j];
    float sc = a/(1.f+__expf(-a));
    float hval = g_h[n*HID + j] + g_xself[n*HID + j] + sc;
    hsm[nn][j] = hval;
    __syncwarp();
    float accv = 0.f;
    #pragma unroll
    for (int u = 0; u < 32; ++u) accv = fmaf(hsm[nn][u], pj[u*32+j], accv);
    out[n*32 + j] = accv * 0.17677669529663687f;
}

extern "C" void kernel_launch(void* const* d_in, const int* in_sizes, int n_in,
                              void* d_out, int out_size) {
    const float* x      = (const float*)d_in[0];
    const float* pos    = (const float*)d_in[1];
    const int*   ei     = (const int*)  d_in[2];
    const float* embed  = (const float*)d_in[3];
    const float* proj   = (const float*)d_in[4];
    const float* lin_ws = (const float*)d_in[5];
    const float* lin_wv = (const float*)d_in[6];
    const float* sc_ws  = (const float*)d_in[7];
    const float* sc_wv  = (const float*)d_in[8];
    const float* w1     = (const float*)d_in[9];
    const float* b1     = (const float*)d_in[10];
    const float* w2     = (const float*)d_in[11];
    const float* b2     = (const float*)d_in[12];
    const float* w3     = (const float*)d_in[13];
    const float* b3     = (const float*)d_in[14];

    cudaFuncSetAttribute(k_msg, cudaFuncAttributeMaxDynamicSharedMemorySize, (int)sizeof(SmemT));

    kA<<<936, 256>>>(pos, ei, x, embed, w3, b3);
    k_radial4<<<768, 256>>>(w1, b1, w2, b2);
    for (int l = 0; l < 4; ++l) {
        k_fuse<<<64, 256>>>(l > 0 ? 1 : 0,
                            lin_ws + l*1024, lin_wv + l*256, sc_ws + l*1024, sc_wv + l*256);
        k_msg<<<384, 512, sizeof(SmemT)>>>(l, ei);
    }
    k_fin<<<256, 256>>>(proj, (float*)d_out);
}